// round 13
// baseline (speedup 1.0000x reference)
#include <cuda_runtime.h>
#include <cuda_bf16.h>
#include <math.h>
#include <stdint.h>

#define BB 2
#define TT 2048
#define DIN 1024
#define EE 64
#define HH 16
#define EH 1024
#define MM (BB*TT)

// bf16 split operands for QKV GEMM
__device__ __align__(16) __nv_bfloat16 g_xhi[MM*DIN];
__device__ __align__(16) __nv_bfloat16 g_xlo[MM*DIN];
__device__ __align__(16) __nv_bfloat16 g_wthi[3*EH*DIN];   // [z][n][k]
__device__ __align__(16) __nv_bfloat16 g_wtlo[3*EH*DIN];
// fp32 staging: q,k in [b,h,t,e]; v in [b,h,e,t]
__device__ __align__(16) float g_qf[BB*HH*TT*EE];
__device__ __align__(16) float g_kf[BB*HH*TT*EE];
__device__ __align__(16) float g_vf[BB*HH*EE*TT];
// bf16 hi/lo for attention (q,k [b,h,t,e]; v [b,h,e,t]); q scaled 0.125*log2e
__device__ __align__(16) __nv_bfloat16 g_qbh[BB*HH*TT*EE];
__device__ __align__(16) __nv_bfloat16 g_qbl[BB*HH*TT*EE];
__device__ __align__(16) __nv_bfloat16 g_kbh[BB*HH*TT*EE];
__device__ __align__(16) __nv_bfloat16 g_kbl[BB*HH*TT*EE];
__device__ __align__(16) __nv_bfloat16 g_vbh[BB*HH*EE*TT];
__device__ __align__(16) __nv_bfloat16 g_vbl[BB*HH*EE*TT];
// attention output [b,h,t,e] fp32
__device__ __align__(16) float g_o[BB*HH*TT*EE];

__device__ __forceinline__ void ld4(float* d, const float* s) {
    float4 t = *(const float4*)s;
    d[0] = t.x; d[1] = t.y; d[2] = t.z; d[3] = t.w;
}
__device__ __forceinline__ void cpa16(uint32_t dst, const void* src) {
    asm volatile("cp.async.cg.shared.global [%0], [%1], 16;\n" :: "r"(dst), "l"(src));
}
__device__ __forceinline__ void cp_commit() {
    asm volatile("cp.async.commit_group;\n");
}
template<int N> __device__ __forceinline__ void cp_wait() {
    asm volatile("cp.async.wait_group %0;\n" :: "n"(N));
}
__device__ __forceinline__ uint32_t smem_u32(const void* p) {
    uint32_t a;
    asm("{ .reg .u64 t; cvta.to.shared.u64 t, %1; cvt.u32.u64 %0, t; }" : "=r"(a) : "l"(p));
    return a;
}
__device__ __forceinline__ void mma_bf16(float* c, const uint32_t* a,
                                         uint32_t b0, uint32_t b1) {
    asm volatile(
        "mma.sync.aligned.m16n8k16.row.col.f32.bf16.bf16.f32 "
        "{%0,%1,%2,%3}, {%4,%5,%6,%7}, {%8,%9}, {%0,%1,%2,%3};"
        : "+f"(c[0]), "+f"(c[1]), "+f"(c[2]), "+f"(c[3])
        : "r"(a[0]), "r"(a[1]), "r"(a[2]), "r"(a[3]), "r"(b0), "r"(b1));
}
__device__ __forceinline__ void ldm4(uint32_t* r, uint32_t addr) {
    asm volatile("ldmatrix.sync.aligned.m8n8.x4.shared.b16 {%0,%1,%2,%3}, [%4];"
        : "=r"(r[0]), "=r"(r[1]), "=r"(r[2]), "=r"(r[3]) : "r"(addr));
}
// pack (f0 -> low half, f1 -> high half) into bf16x2 hi + residual lo
__device__ __forceinline__ void pack_hilo(float f0, float f1,
                                          uint32_t& hi, uint32_t& lo) {
    __nv_bfloat162 h = __floats2bfloat162_rn(f0, f1);
    float r0 = f0 - __bfloat162float(h.x);
    float r1 = f1 - __bfloat162float(h.y);
    __nv_bfloat162 l = __floats2bfloat162_rn(r0, r1);
    hi = *reinterpret_cast<uint32_t*>(&h);
    lo = *reinterpret_cast<uint32_t*>(&l);
}

// ---------------------------------------------------------------------------
// Prep: X f32 -> bf16 hi/lo
// ---------------------------------------------------------------------------
__global__ __launch_bounds__(256) void conv_x(const float* __restrict__ x)
{
    int i = (blockIdx.x * 256 + threadIdx.x) * 4;
    float4 v = *(const float4*)(x + i);
    uint32_t h01, l01, h23, l23;
    pack_hilo(v.x, v.y, h01, l01);
    pack_hilo(v.z, v.w, h23, l23);
    *(uint32_t*)(g_xhi + i)     = h01;
    *(uint32_t*)(g_xhi + i + 2) = h23;
    *(uint32_t*)(g_xlo + i)     = l01;
    *(uint32_t*)(g_xlo + i + 2) = l23;
}

// ---------------------------------------------------------------------------
// Prep: W [k][n] f32 -> Wt [n][k] bf16 hi/lo, for each of Wq,Wk,Wv
// ---------------------------------------------------------------------------
__global__ __launch_bounds__(256) void conv_w(
    const float* __restrict__ Wq, const float* __restrict__ Wk,
    const float* __restrict__ Wv)
{
    const int z = blockIdx.z;
    const float* W = (z == 0) ? Wq : (z == 1) ? Wk : Wv;
    __shared__ float t[32][33];
    const int k0 = blockIdx.x * 32, n0 = blockIdx.y * 32;
    const int x = threadIdx.x & 31, y = threadIdx.x >> 5;
    #pragma unroll
    for (int i = 0; i < 32; i += 8)
        t[y + i][x] = W[(k0 + y + i) * EH + n0 + x];
    __syncthreads();
    #pragma unroll
    for (int i = 0; i < 32; i += 8) {
        float v = t[x][y + i];
        __nv_bfloat16 hi = __float2bfloat16(v);
        __nv_bfloat16 lo = __float2bfloat16(v - __bfloat162float(hi));
        size_t idx = (size_t)z * EH * DIN + (size_t)(n0 + y + i) * DIN + k0 + x;
        g_wthi[idx] = hi;
        g_wtlo[idx] = lo;
    }
}

// ---------------------------------------------------------------------------
// Kernel 1: QKV via mma.sync bf16 (hi/lo 3-term compensation).
// 4-stage cp.async pipeline, k-tile 32 (96 iters), distance-3 prefetch,
// ONE wait<2> + ONE barrier per k-tile. ldmatrix frags; fp32 staging epilogue.
// CTA 128m x 128n, 8 warps (2m x 4n), warp tile 64x32.
// ---------------------------------------------------------------------------
#define ASTR 40
#define QB (128*ASTR*2)        // 10240 B per operand per stage
#define QKV_SMEM (8*QB)        // A0..A3 B0..B3 = 81920 B

__global__ __launch_bounds__(256, 2) void qkv_mma()
{
    extern __shared__ __align__(16) char qsm[];
    const uint32_t ub = smem_u32(qsm);

    const int z = blockIdx.z;
    const int m0 = blockIdx.x * 128;
    const int n0 = blockIdx.y * 128;
    const int tid = threadIdx.x;
    const int wid = tid >> 5, lane = tid & 31;
    const int wm = wid >> 2, wn = wid & 3;
    const int lg = lane >> 2, lt = lane & 3;
    const int arow = ((lane >> 3) & 1) * 8 + (lane & 7);
    const int acol = ((lane >> 4) & 1) * 8;
    const int brow = ((lane >> 4) & 1) * 8 + (lane & 7);
    const int bcol = ((lane >> 3) & 1) * 8;

    const __nv_bfloat16* whi = g_wthi + (size_t)z * EH * DIN;
    const __nv_bfloat16* wlo = g_wtlo + (size_t)z * EH * DIN;

    auto fill = [&](int c, int stg) {
        const int pass = c >> 5;
        const int k0 = (c & 31) * 32;
        const __nv_bfloat16* A = (pass == 1) ? g_xlo : g_xhi;
        const __nv_bfloat16* B = (pass == 2) ? wlo : whi;
        const uint32_t ab = ub + stg * QB;
        const uint32_t bb = ub + (4 + stg) * QB;
        #pragma unroll
        for (int l = 0; l < 2; l++) {
            int s = tid + l * 256, r = s >> 2, cg = s & 3;
            uint32_t off = (r * ASTR + cg * 8) * 2;
            cpa16(ab + off, A + (size_t)(m0 + r) * DIN + k0 + cg * 8);
            cpa16(bb + off, B + (size_t)(n0 + r) * DIN + k0 + cg * 8);
        }
        cp_commit();
    };

    float acc[4][4][4] = {};

    fill(0, 0);
    fill(1, 1);
    fill(2, 2);
    for (int c = 0; c < 96; c++) {
        const int stg = c & 3;
        cp_wait<2>();        // tile c complete; c+1, c+2 may be in flight
        __syncthreads();     // all warps done with buf (c+3)%4 (iter c-1)

        fill(c + 3 < 96 ? c + 3 : 0, (c + 3) & 3);   // distance-3 prefetch

        const uint32_t sAb = ub + stg * QB;
        const uint32_t sBb = ub + (4 + stg) * QB;
        #pragma unroll
        for (int ks = 0; ks < 2; ks++) {
            uint32_t af[4][4], bfr[2][4];
            #pragma unroll
            for (int i = 0; i < 4; i++)
                ldm4(af[i], sAb + (((wm*64 + i*16 + arow) * ASTR) + ks*16 + acol) * 2);
            #pragma unroll
            for (int jp = 0; jp < 2; jp++)
                ldm4(bfr[jp], sBb + (((wn*32 + jp*16 + brow) * ASTR) + ks*16 + bcol) * 2);
            #pragma unroll
            for (int i = 0; i < 4; i++)
                #pragma unroll
                for (int j = 0; j < 4; j++)
                    mma_bf16(acc[i][j], af[i], bfr[j >> 1][(j & 1)*2], bfr[j >> 1][(j & 1)*2 + 1]);
        }
    }

    // epilogue: de-interleave heads (n = e*16 + h), fp32 staging.
    float* dst = (z == 0) ? g_qf : (z == 1) ? g_kf : g_vf;
    const int emajor = (z == 2);
    #pragma unroll
    for (int i = 0; i < 4; i++) {
        #pragma unroll
        for (int j = 0; j < 4; j++) {
            #pragma unroll
            for (int rr = 0; rr < 2; rr++) {
                int m = m0 + wm * 64 + i * 16 + lg + rr * 8;
                int b = m >> 11, t = m & 2047;
                #pragma unroll
                for (int cc = 0; cc < 2; cc++) {
                    int n = n0 + wn * 32 + j * 8 + lt * 2 + cc;
                    int e = n >> 4, h = n & 15;
                    size_t bh = (size_t)(b * HH + h);
                    float v = acc[i][j][rr * 2 + cc];
                    if (emajor) dst[(bh * EE + e) * TT + t] = v;
                    else        dst[(bh * TT + t) * EE + e] = v;
                }
            }
        }
    }
}

// ---------------------------------------------------------------------------
// conv_qkv: fp32 staging -> bf16 hi/lo (Q scaled 0.125*log2(e) for exp2f).
// 4 independent float4 per thread (batched loads -> MLP 4).
// ---------------------------------------------------------------------------
#define CONVN (BB*HH*TT*EE)     // elements per tensor
#define CONVSTRIDE (CONVN/4)    // 4 chunks

__global__ __launch_bounds__(256) void conv_qkv()
{
    const int z = blockIdx.y;
    const float* src = (z == 0) ? g_qf : (z == 1) ? g_kf : g_vf;
    __nv_bfloat16* dh = (z == 0) ? g_qbh : (z == 1) ? g_kbh : g_vbh;
    __nv_bfloat16* dl = (z == 0) ? g_qbl : (z == 1) ? g_kbl : g_vbl;
    const float sc = (z == 0) ? 0.125f * 1.4426950408889634f : 1.0f;
    const size_t base = ((size_t)blockIdx.x * 256 + threadIdx.x) * 4;

    float4 v[4];
    #pragma unroll
    for (int k = 0; k < 4; k++)
        v[k] = *(const float4*)(src + base + (size_t)k * CONVSTRIDE);

    #pragma unroll
    for (int k = 0; k < 4; k++) {
        size_t i = base + (size_t)k * CONVSTRIDE;
        float4 w = v[k];
        w.x *= sc; w.y *= sc; w.z *= sc; w.w *= sc;
        uint32_t h01, l01, h23, l23;
        pack_hilo(w.x, w.y, h01, l01);
        pack_hilo(w.z, w.w, h23, l23);
        *(uint32_t*)(dh + i)     = h01;
        *(uint32_t*)(dh + i + 2) = h23;
        *(uint32_t*)(dl + i)     = l01;
        *(uint32_t*)(dl + i + 2) = l23;
    }
}

// ---------------------------------------------------------------------------
// Kernel 2: flash-attention on mma.sync, causal, hi/lo compensated, ldmatrix.
// 4-stage K/V pipeline (hi/lo), distance-3 prefetch, ONE wait<2> + ONE
// barrier per iteration. Softmax in log2 domain. Key tiles of 64.
// CTA = 128 rows of one (b,h); 8 warps x 16 rows.
// ---------------------------------------------------------------------------
#define KSTR 72
#define KVBYTES (64*KSTR*2)     // 9216 B per buffer
#define NSTG 4
#define ATTN_SMEM (4*NSTG*KVBYTES)  // Kh,Kl,Vh,Vl x 4 stages = 147456 B

__global__ __launch_bounds__(256) void attn_mma()
{
    extern __shared__ __align__(16) char asm_[];
    const uint32_t ub = smem_u32(asm_);

    const int qt = (int)(gridDim.x - 1) - (int)blockIdx.x;  // big tiles first
    const int bh = blockIdx.y;
    const int r0 = qt * 128;
    const int tid = threadIdx.x;
    const int wid = tid >> 5, lane = tid & 31;
    const int lg = lane >> 2, lt = lane & 3;
    const int krow = ((lane >> 4) & 1) * 8 + (lane & 7);
    const int kcol = ((lane >> 3) & 1) * 8;

    auto issueKV = [&](int c0, int stg) {
        const uint32_t bKh = ub + stg * KVBYTES;
        const uint32_t bKl = ub + (NSTG + stg) * KVBYTES;
        const uint32_t bVh = ub + (2*NSTG + stg) * KVBYTES;
        const uint32_t bVl = ub + (3*NSTG + stg) * KVBYTES;
        #pragma unroll
        for (int l = 0; l < 4; l++) {
            int s = tid + l * 256;
            int arr = s >> 9, idx = s & 511;
            int r = idx >> 3, g = idx & 7;
            const __nv_bfloat16* src = (arr ? g_kbl : g_kbh)
                + ((size_t)bh * TT + c0 + r) * EE + g * 8;
            cpa16((arr ? bKl : bKh) + (r * KSTR + g * 8) * 2, src);
        }
        #pragma unroll
        for (int l = 0; l < 4; l++) {
            int s = tid + l * 256;
            int arr = s >> 9, idx = s & 511;
            int r = idx >> 3, g = idx & 7;
            const __nv_bfloat16* src = (arr ? g_vbl : g_vbh)
                + ((size_t)bh * EE + r) * TT + c0 + g * 8;
            cpa16((arr ? bVl : bVh) + (r * KSTR + g * 8) * 2, src);
        }
        cp_commit();
    };

    const int nkt = 2 * qt + 2;   // >= 2 always
    issueKV(0, 0);
    issueKV(64, 1);
    issueKV(nkt > 2 ? 128 : 0, 2);

    // Q fragments, register-resident (Q pre-scaled by 0.125*log2e)
    const int ra = r0 + wid * 16 + lg, rb = ra + 8;
    uint32_t qh[4][4], ql[4][4];
    {
        const __nv_bfloat16* qhp = g_qbh + (size_t)bh * TT * EE;
        const __nv_bfloat16* qlp = g_qbl + (size_t)bh * TT * EE;
        #pragma unroll
        for (int ks = 0; ks < 4; ks++) {
            int e0 = ks * 16 + 2 * lt;
            qh[ks][0] = *(const uint32_t*)(qhp + (size_t)ra * EE + e0);
            qh[ks][1] = *(const uint32_t*)(qhp + (size_t)rb * EE + e0);
            qh[ks][2] = *(const uint32_t*)(qhp + (size_t)ra * EE + e0 + 8);
            qh[ks][3] = *(const uint32_t*)(qhp + (size_t)rb * EE + e0 + 8);
            ql[ks][0] = *(const uint32_t*)(qlp + (size_t)ra * EE + e0);
            ql[ks][1] = *(const uint32_t*)(qlp + (size_t)rb * EE + e0);
            ql[ks][2] = *(const uint32_t*)(qlp + (size_t)ra * EE + e0 + 8);
            ql[ks][3] = *(const uint32_t*)(qlp + (size_t)rb * EE + e0 + 8);
        }
    }

    float os[8][4] = {};
    float mi_a = -INFINITY, mi_b = -INFINITY, li_a = 0.f, li_b = 0.f;

    for (int kt = 0; kt < nkt; kt++) {
        const int c0 = kt * 64;
        const int stg = kt & 3;
        const uint32_t uKhB = ub + stg * KVBYTES;
        const uint32_t uKlB = ub + (NSTG + stg) * KVBYTES;
        const uint32_t uVhB = ub + (2*NSTG + stg) * KVBYTES;
        const uint32_t uVlB = ub + (3*NSTG + stg) * KVBYTES;

        cp_wait<2>();        // KV(kt) complete; kt+1, kt+2 may be in flight
        __syncthreads();     // frees buf (kt+3)%4 for refill

        // S = Q K^T (3 compensated terms); accumulators interleaved
        float cs[8][4] = {};
        #pragma unroll
        for (int ks = 0; ks < 4; ks++) {
            const uint32_t co = ks * 16 + kcol;
            #pragma unroll
            for (int jp = 0; jp < 4; jp++) {
                uint32_t kh[4], kl[4];
                uint32_t off = (((jp*16 + krow) * KSTR) + co) * 2;
                ldm4(kh, uKhB + off);
                ldm4(kl, uKlB + off);
                mma_bf16(cs[2*jp],     qh[ks], kh[0], kh[1]);
                mma_bf16(cs[2*jp + 1], qh[ks], kh[2], kh[3]);
                mma_bf16(cs[2*jp],     ql[ks], kh[0], kh[1]);
                mma_bf16(cs[2*jp + 1], ql[ks], kh[2], kh[3]);
                mma_bf16(cs[2*jp],     qh[ks], kl[0], kl[1]);
                mma_bf16(cs[2*jp + 1], qh[ks], kl[2], kl[3]);
            }
        }

        // distance-3 prefetch (dummy at tail keeps wait-group counting)
        issueKV(kt + 3 < nkt ? c0 + 192 : 0, (kt + 3) & 3);

        if (kt >= 2 * qt) {  // causal mask (only last two tiles)
            #pragma unroll
            for (int jt = 0; jt < 8; jt++)
                #pragma unroll
                for (int cc = 0; cc < 2; cc++) {
                    int col = c0 + jt * 8 + 2 * lt + cc;
                    if (col > ra) cs[jt][cc]     = -1e30f;
                    if (col > rb) cs[jt][2 + cc] = -1e30f;
                }
        }

        // online softmax (log2 domain) over rows ra / rb
        float ma = -1e30f, mb = -1e30f;
        #pragma unroll
        for (int jt = 0; jt < 8; jt++) {
            ma = fmaxf(ma, fmaxf(cs[jt][0], cs[jt][1]));
            mb = fmaxf(mb, fmaxf(cs[jt][2], cs[jt][3]));
        }
        ma = fmaxf(ma, __shfl_xor_sync(0xffffffffu, ma, 1));
        ma = fmaxf(ma, __shfl_xor_sync(0xffffffffu, ma, 2));
        mb = fmaxf(mb, __shfl_xor_sync(0xffffffffu, mb, 1));
        mb = fmaxf(mb, __shfl_xor_sync(0xffffffffu, mb, 2));
        float nma = fmaxf(mi_a, ma), nmb = fmaxf(mi_b, mb);
        float ca = exp2f(mi_a - nma), cb = exp2f(mi_b - nmb);
        float sa = 0.f, sb = 0.f;
        #pragma unroll
        for (int jt = 0; jt < 8; jt++) {
            cs[jt][0] = exp2f(cs[jt][0] - nma); sa += cs[jt][0];
            cs[jt][1] = exp2f(cs[jt][1] - nma); sa += cs[jt][1];
            cs[jt][2] = exp2f(cs[jt][2] - nmb); sb += cs[jt][2];
            cs[jt][3] = exp2f(cs[jt][3] - nmb); sb += cs[jt][3];
        }
        sa += __shfl_xor_sync(0xffffffffu, sa, 1);
        sa += __shfl_xor_sync(0xffffffffu, sa, 2);
        sb += __shfl_xor_sync(0xffffffffu, sb, 1);
        sb += __shfl_xor_sync(0xffffffffu, sb, 2);
        li_a = li_a * ca + sa; mi_a = nma;
        li_b = li_b * cb + sb; mi_b = nmb;
        #pragma unroll
        for (int jt = 0; jt < 8; jt++) {
            os[jt][0] *= ca; os[jt][1] *= ca;
            os[jt][2] *= cb; os[jt][3] *= cb;
        }

        // P fragments (hi/lo) straight from registers
        uint32_t phi[4][4], plo[4][4];
        #pragma unroll
        for (int cc = 0; cc < 4; cc++) {
            pack_hilo(cs[2*cc][0],   cs[2*cc][1],   phi[cc][0], plo[cc][0]);
            pack_hilo(cs[2*cc][2],   cs[2*cc][3],   phi[cc][1], plo[cc][1]);
            pack_hilo(cs[2*cc+1][0], cs[2*cc+1][1], phi[cc][2], plo[cc][2]);
            pack_hilo(cs[2*cc+1][2], cs[2*cc+1][3], phi[cc][3], plo[cc][3]);
        }

        // O += P V (3 compensated terms)
        #pragma unroll
        for (int cc = 0; cc < 4; cc++) {
            const uint32_t co = cc * 16 + kcol;
            #pragma unroll
            for (int jp = 0; jp < 4; jp++) {
                uint32_t vh[4], vl[4];
                uint32_t off = (((jp*16 + krow) * KSTR) + co) * 2;
                ldm4(vh, uVhB + off);
                ldm4(vl, uVlB + off);
                mma_bf16(os[2*jp],     phi[cc], vh[0], vh[1]);
                mma_bf16(os[2*jp + 1], phi[cc], vh[2], vh[3]);
                mma_bf16(os[2*jp],     plo[cc], vh[0], vh[1]);
                mma_bf16(os[2*jp + 1], plo[cc], vh[2], vh[3]);
                mma_bf16(os[2*jp],     phi[cc], vl[0], vl[1]);
                mma_bf16(os[2*jp + 1], phi[cc], vl[2], vl[3]);
            }
        }
    }

    // epilogue: normalize, write [b,h,t,e]
    const float ia = 1.0f / li_a, ib = 1.0f / li_b;
    #pragma unroll
    for (int jt = 0; jt < 8; jt++) {
        int e0 = jt * 8 + 2 * lt;
        float2 wa = make_float2(os[jt][0] * ia, os[jt][1] * ia);
        float2 wb = make_float2(os[jt][2] * ib, os[jt][3] * ib);
        *(float2*)(g_o + ((size_t)bh * TT + ra) * EE + e0) = wa;
        *(float2*)(g_o + ((size_t)bh * TT + rb) * EE + e0) = wb;
    }
}

// ---------------------------------------------------------------------------
// Kernel 3a: out = bias broadcast
// ---------------------------------------------------------------------------
__global__ __launch_bounds__(256) void init_out(const float* __restrict__ bu,
                                                float* __restrict__ out)
{
    int i = blockIdx.x * 256 + threadIdx.x;
    out[i] = bu[i & 63];
}

// ---------------------------------------------------------------------------
// Kernel 3b: output projection as sum of per-head GEMMs (coalesced A loads).
// ---------------------------------------------------------------------------
__global__ __launch_bounds__(256) void proj_kernel(
    const float* __restrict__ Wu,
    float* __restrict__ out)
{
    __shared__ __align__(16) float As[64*68];  // [e][m] transposed on write
    __shared__ __align__(16) float Bs[64*68];  // [e][n]

    const int m0 = blockIdx.x * 64;
    const int tid = threadIdx.x;
    const int ty = tid >> 4, tx = tid & 15;
    const int b = m0 >> 11, t0 = m0 & 2047;

    float acc[4][4] = {};

    for (int hh = 0; hh < 4; hh++) {
        const int h = blockIdx.y * 4 + hh;
        __syncthreads();
        const float* op = g_o + ((size_t)(b * HH + h) * TT + t0) * EE;
        for (int s = tid; s < 1024; s += 256) {
            int r = s >> 4, g = s & 15;
            float4 v = *(const float4*)(op + r * EE + g * 4);
            As[(g*4 + 0)*68 + r] = v.x;
            As[(g*4 + 1)*68 + r] = v.y;
            As[(g*4 + 2)*68 + r] = v.z;
            As[(g*4 + 3)*68 + r] = v.w;
        }
        for (int s = tid; s < 1024; s += 256) {
            int e = s >> 4, g = s & 15;
            *(float4*)(Bs + e*68 + g*4) =
                *(const float4*)(Wu + (size_t)(e * HH + h) * EE + g * 4);
        }
        __syncthreads();

        #pragma unroll 8
        for (int e = 0; e < 64; e++) {
            float a[4], bv[4];
            ld4(a,  As + e*68 + ty*4);
            ld4(bv, Bs + e*68 + tx*4);
            #pragma unroll
            for (int i = 0; i < 4; i++)
                #pragma unroll
                for (int j = 0; j < 4; j++)
                    acc[i][j] += a[i] * bv[j];
        }
    }

    #pragma unroll
    for (int i = 0; i < 4; i++) {
        int gm = m0 + ty*4 + i;
        #pragma unroll
        for (int j = 0; j < 4; j++)
            atomicAdd(out + (size_t)gm * EE + tx*4 + j, acc[i][j]);
    }
}

// ---------------------------------------------------------------------------
extern "C" void kernel_launch(void* const* d_in, const int* in_sizes, int n_in,
                              void* d_out, int out_size)
{
    const float* inp = (const float*)d_in[0];
    // d_in[1] is the causal mask; causality is implemented directly.
    const float* Wq = (const float*)d_in[2];
    const float* Wk = (const float*)d_in[3];
    const float* Wv = (const float*)d_in[4];
    const float* Wu = (const float*)d_in[5];
    const float* bu = (const float*)d_in[6];
    float* out = (float*)d_out;

    cudaFuncSetAttribute(qkv_mma,
                         cudaFuncAttributeMaxDynamicSharedMemorySize, QKV_SMEM);
    cudaFuncSetAttribute(attn_mma,
                         cudaFuncAttributeMaxDynamicSharedMemorySize, ATTN_SMEM);

    conv_x<<<MM*DIN/1024, 256>>>(inp);
    conv_w<<<dim3(DIN/32, EH/32, 3), 256>>>(Wq, Wk, Wv);

    qkv_mma<<<dim3(MM/128, EH/128, 3), 256, QKV_SMEM>>>();

    conv_qkv<<<dim3(CONVN/4096, 3), 256>>>();

    attn_mma<<<dim3(TT/128, BB*HH), 256, ATTN_SMEM>>>();

    init_out<<<(MM*EE)/256, 256>>>(bu, out);
    proj_kernel<<<dim3(MM/64, 4), 256>>>(Wu, out);
}

// round 14
// speedup vs baseline: 1.0105x; 1.0105x over previous
#include <cuda_runtime.h>
#include <cuda_bf16.h>
#include <math.h>
#include <stdint.h>

#define BB 2
#define TT 2048
#define DIN 1024
#define EE 64
#define HH 16
#define EH 1024
#define MM (BB*TT)

// bf16 split operands for QKV GEMM
__device__ __align__(16) __nv_bfloat16 g_xhi[MM*DIN];
__device__ __align__(16) __nv_bfloat16 g_xlo[MM*DIN];
__device__ __align__(16) __nv_bfloat16 g_wthi[3*EH*DIN];   // [z][n][k]
__device__ __align__(16) __nv_bfloat16 g_wtlo[3*EH*DIN];
// fp32 staging: q,k in [b,h,t,e]; v in [b,h,e,t]
__device__ __align__(16) float g_qf[BB*HH*TT*EE];
__device__ __align__(16) float g_kf[BB*HH*TT*EE];
__device__ __align__(16) float g_vf[BB*HH*EE*TT];
// bf16 hi/lo for attention (q,k [b,h,t,e]; v [b,h,e,t]); q scaled 0.125*log2e
__device__ __align__(16) __nv_bfloat16 g_qbh[BB*HH*TT*EE];
__device__ __align__(16) __nv_bfloat16 g_qbl[BB*HH*TT*EE];
__device__ __align__(16) __nv_bfloat16 g_kbh[BB*HH*TT*EE];
__device__ __align__(16) __nv_bfloat16 g_kbl[BB*HH*TT*EE];
__device__ __align__(16) __nv_bfloat16 g_vbh[BB*HH*EE*TT];
__device__ __align__(16) __nv_bfloat16 g_vbl[BB*HH*EE*TT];
// attention output [b,h,t,e] fp32
__device__ __align__(16) float g_o[BB*HH*TT*EE];

__device__ __forceinline__ void ld4(float* d, const float* s) {
    float4 t = *(const float4*)s;
    d[0] = t.x; d[1] = t.y; d[2] = t.z; d[3] = t.w;
}
__device__ __forceinline__ void cpa16(uint32_t dst, const void* src) {
    asm volatile("cp.async.cg.shared.global [%0], [%1], 16;\n" :: "r"(dst), "l"(src));
}
__device__ __forceinline__ void cp_commit() {
    asm volatile("cp.async.commit_group;\n");
}
template<int N> __device__ __forceinline__ void cp_wait() {
    asm volatile("cp.async.wait_group %0;\n" :: "n"(N));
}
__device__ __forceinline__ uint32_t smem_u32(const void* p) {
    uint32_t a;
    asm("{ .reg .u64 t; cvta.to.shared.u64 t, %1; cvt.u32.u64 %0, t; }" : "=r"(a) : "l"(p));
    return a;
}
__device__ __forceinline__ void mma_bf16(float* c, const uint32_t* a,
                                         uint32_t b0, uint32_t b1) {
    asm volatile(
        "mma.sync.aligned.m16n8k16.row.col.f32.bf16.bf16.f32 "
        "{%0,%1,%2,%3}, {%4,%5,%6,%7}, {%8,%9}, {%0,%1,%2,%3};"
        : "+f"(c[0]), "+f"(c[1]), "+f"(c[2]), "+f"(c[3])
        : "r"(a[0]), "r"(a[1]), "r"(a[2]), "r"(a[3]), "r"(b0), "r"(b1));
}
__device__ __forceinline__ void ldm4(uint32_t* r, uint32_t addr) {
    asm volatile("ldmatrix.sync.aligned.m8n8.x4.shared.b16 {%0,%1,%2,%3}, [%4];"
        : "=r"(r[0]), "=r"(r[1]), "=r"(r[2]), "=r"(r[3]) : "r"(addr));
}
// pack (f0 -> low half, f1 -> high half) into bf16x2 hi + residual lo
__device__ __forceinline__ void pack_hilo(float f0, float f1,
                                          uint32_t& hi, uint32_t& lo) {
    __nv_bfloat162 h = __floats2bfloat162_rn(f0, f1);
    float r0 = f0 - __bfloat162float(h.x);
    float r1 = f1 - __bfloat162float(h.y);
    __nv_bfloat162 l = __floats2bfloat162_rn(r0, r1);
    hi = *reinterpret_cast<uint32_t*>(&h);
    lo = *reinterpret_cast<uint32_t*>(&l);
}

// ---------------------------------------------------------------------------
// Prep: X f32 -> bf16 hi/lo
// ---------------------------------------------------------------------------
__global__ __launch_bounds__(256) void conv_x(const float* __restrict__ x)
{
    int i = (blockIdx.x * 256 + threadIdx.x) * 4;
    float4 v = *(const float4*)(x + i);
    uint32_t h01, l01, h23, l23;
    pack_hilo(v.x, v.y, h01, l01);
    pack_hilo(v.z, v.w, h23, l23);
    *(uint32_t*)(g_xhi + i)     = h01;
    *(uint32_t*)(g_xhi + i + 2) = h23;
    *(uint32_t*)(g_xlo + i)     = l01;
    *(uint32_t*)(g_xlo + i + 2) = l23;
}

// ---------------------------------------------------------------------------
// Prep: W [k][n] f32 -> Wt [n][k] bf16 hi/lo, for each of Wq,Wk,Wv
// ---------------------------------------------------------------------------
__global__ __launch_bounds__(256) void conv_w(
    const float* __restrict__ Wq, const float* __restrict__ Wk,
    const float* __restrict__ Wv)
{
    const int z = blockIdx.z;
    const float* W = (z == 0) ? Wq : (z == 1) ? Wk : Wv;
    __shared__ float t[32][33];
    const int k0 = blockIdx.x * 32, n0 = blockIdx.y * 32;
    const int x = threadIdx.x & 31, y = threadIdx.x >> 5;
    #pragma unroll
    for (int i = 0; i < 32; i += 8)
        t[y + i][x] = W[(k0 + y + i) * EH + n0 + x];
    __syncthreads();
    #pragma unroll
    for (int i = 0; i < 32; i += 8) {
        float v = t[x][y + i];
        __nv_bfloat16 hi = __float2bfloat16(v);
        __nv_bfloat16 lo = __float2bfloat16(v - __bfloat162float(hi));
        size_t idx = (size_t)z * EH * DIN + (size_t)(n0 + y + i) * DIN + k0 + x;
        g_wthi[idx] = hi;
        g_wtlo[idx] = lo;
    }
}

// ---------------------------------------------------------------------------
// Kernel 1: QKV via mma.sync bf16 (hi/lo 3-term compensation).
// Triple-buffered cp.async, k-tile 32 (96 iters), distance-2 prefetch,
// ONE wait + ONE barrier per k-tile. ldmatrix frags; fp32 staging epilogue.
// CTA 128m x 128n, 8 warps (2m x 4n), warp tile 64x32.  (R11-proven config.)
// ---------------------------------------------------------------------------
#define ASTR 40
#define QB (128*ASTR*2)        // 10240 B per operand per stage
#define QKV_SMEM (6*QB)        // A0 A1 A2 B0 B1 B2 = 61440 B

__global__ __launch_bounds__(256, 2) void qkv_mma()
{
    extern __shared__ __align__(16) char qsm[];
    const uint32_t ub = smem_u32(qsm);

    const int z = blockIdx.z;
    const int m0 = blockIdx.x * 128;
    const int n0 = blockIdx.y * 128;
    const int tid = threadIdx.x;
    const int wid = tid >> 5, lane = tid & 31;
    const int wm = wid >> 2, wn = wid & 3;
    const int lg = lane >> 2, lt = lane & 3;
    const int arow = ((lane >> 3) & 1) * 8 + (lane & 7);
    const int acol = ((lane >> 4) & 1) * 8;
    const int brow = ((lane >> 4) & 1) * 8 + (lane & 7);
    const int bcol = ((lane >> 3) & 1) * 8;

    const __nv_bfloat16* whi = g_wthi + (size_t)z * EH * DIN;
    const __nv_bfloat16* wlo = g_wtlo + (size_t)z * EH * DIN;

    auto fill = [&](int c, int stg) {
        const int pass = c >> 5;
        const int k0 = (c & 31) * 32;
        const __nv_bfloat16* A = (pass == 1) ? g_xlo : g_xhi;
        const __nv_bfloat16* B = (pass == 2) ? wlo : whi;
        const uint32_t ab = ub + stg * QB;
        const uint32_t bb = ub + (3 + stg) * QB;
        #pragma unroll
        for (int l = 0; l < 2; l++) {
            int s = tid + l * 256, r = s >> 2, cg = s & 3;
            uint32_t off = (r * ASTR + cg * 8) * 2;
            cpa16(ab + off, A + (size_t)(m0 + r) * DIN + k0 + cg * 8);
            cpa16(bb + off, B + (size_t)(n0 + r) * DIN + k0 + cg * 8);
        }
        cp_commit();
    };

    float acc[4][4][4] = {};

    fill(0, 0);
    fill(1, 1);
    for (int c = 0; c < 96; c++) {
        const int stg = c % 3;
        cp_wait<1>();        // tile c complete; tile c+1 may be in flight
        __syncthreads();     // all warps done with buf (c+2)%3 (iter c-1)

        fill(c + 2 < 96 ? c + 2 : 0, (c + 2) % 3);   // distance-2 prefetch

        const uint32_t sAb = ub + stg * QB;
        const uint32_t sBb = ub + (3 + stg) * QB;
        #pragma unroll
        for (int ks = 0; ks < 2; ks++) {
            uint32_t af[4][4], bfr[2][4];
            #pragma unroll
            for (int i = 0; i < 4; i++)
                ldm4(af[i], sAb + (((wm*64 + i*16 + arow) * ASTR) + ks*16 + acol) * 2);
            #pragma unroll
            for (int jp = 0; jp < 2; jp++)
                ldm4(bfr[jp], sBb + (((wn*32 + jp*16 + brow) * ASTR) + ks*16 + bcol) * 2);
            #pragma unroll
            for (int i = 0; i < 4; i++)
                #pragma unroll
                for (int j = 0; j < 4; j++)
                    mma_bf16(acc[i][j], af[i], bfr[j >> 1][(j & 1)*2], bfr[j >> 1][(j & 1)*2 + 1]);
        }
    }

    // epilogue: de-interleave heads (n = e*16 + h), fp32 staging.
    float* dst = (z == 0) ? g_qf : (z == 1) ? g_kf : g_vf;
    const int emajor = (z == 2);
    #pragma unroll
    for (int i = 0; i < 4; i++) {
        #pragma unroll
        for (int j = 0; j < 4; j++) {
            #pragma unroll
            for (int rr = 0; rr < 2; rr++) {
                int m = m0 + wm * 64 + i * 16 + lg + rr * 8;
                int b = m >> 11, t = m & 2047;
                #pragma unroll
                for (int cc = 0; cc < 2; cc++) {
                    int n = n0 + wn * 32 + j * 8 + lt * 2 + cc;
                    int e = n >> 4, h = n & 15;
                    size_t bh = (size_t)(b * HH + h);
                    float v = acc[i][j][rr * 2 + cc];
                    if (emajor) dst[(bh * EE + e) * TT + t] = v;
                    else        dst[(bh * TT + t) * EE + e] = v;
                }
            }
        }
    }
}

// ---------------------------------------------------------------------------
// conv_qkv: fp32 staging -> bf16 hi/lo (Q scaled 0.125*log2(e) for exp2f).
// 4 independent float4 per thread (batched loads -> MLP 4).
// ---------------------------------------------------------------------------
#define CONVN (BB*HH*TT*EE)     // elements per tensor
#define CONVSTRIDE (CONVN/4)    // 4 chunks

__global__ __launch_bounds__(256) void conv_qkv()
{
    const int z = blockIdx.y;
    const float* src = (z == 0) ? g_qf : (z == 1) ? g_kf : g_vf;
    __nv_bfloat16* dh = (z == 0) ? g_qbh : (z == 1) ? g_kbh : g_vbh;
    __nv_bfloat16* dl = (z == 0) ? g_qbl : (z == 1) ? g_kbl : g_vbl;
    const float sc = (z == 0) ? 0.125f * 1.4426950408889634f : 1.0f;
    const size_t base = ((size_t)blockIdx.x * 256 + threadIdx.x) * 4;

    float4 v[4];
    #pragma unroll
    for (int k = 0; k < 4; k++)
        v[k] = *(const float4*)(src + base + (size_t)k * CONVSTRIDE);

    #pragma unroll
    for (int k = 0; k < 4; k++) {
        size_t i = base + (size_t)k * CONVSTRIDE;
        float4 w = v[k];
        w.x *= sc; w.y *= sc; w.z *= sc; w.w *= sc;
        uint32_t h01, l01, h23, l23;
        pack_hilo(w.x, w.y, h01, l01);
        pack_hilo(w.z, w.w, h23, l23);
        *(uint32_t*)(dh + i)     = h01;
        *(uint32_t*)(dh + i + 2) = h23;
        *(uint32_t*)(dl + i)     = l01;
        *(uint32_t*)(dl + i + 2) = l23;
    }
}

// ---------------------------------------------------------------------------
// Kernel 2: flash-attention on mma.sync, causal, hi/lo compensated, ldmatrix.
// Triple-buffered K/V (hi/lo), distance-2 prefetch hoisted right after the
// barrier (buffer (kt+2)%3 is free there), ONE wait + ONE barrier per iter.
// Softmax in log2 domain. Key tiles of 64. (R11-proven config + hoist.)
// ---------------------------------------------------------------------------
#define KSTR 72
#define KVBYTES (64*KSTR*2)     // 9216 B per buffer
#define ATTN_SMEM (12*KVBYTES)  // Kh x3, Kl x3, Vh x3, Vl x3 = 110592 B

__global__ __launch_bounds__(256) void attn_mma()
{
    extern __shared__ __align__(16) char asm_[];
    const uint32_t ub = smem_u32(asm_);

    const int qt = (int)(gridDim.x - 1) - (int)blockIdx.x;  // big tiles first
    const int bh = blockIdx.y;
    const int r0 = qt * 128;
    const int tid = threadIdx.x;
    const int wid = tid >> 5, lane = tid & 31;
    const int lg = lane >> 2, lt = lane & 3;
    const int krow = ((lane >> 4) & 1) * 8 + (lane & 7);
    const int kcol = ((lane >> 3) & 1) * 8;

    auto issueKV = [&](int c0, int buf) {
        const uint32_t bKh = ub + buf * KVBYTES;
        const uint32_t bKl = ub + (3 + buf) * KVBYTES;
        const uint32_t bVh = ub + (6 + buf) * KVBYTES;
        const uint32_t bVl = ub + (9 + buf) * KVBYTES;
        #pragma unroll
        for (int l = 0; l < 4; l++) {
            int s = tid + l * 256;
            int arr = s >> 9, idx = s & 511;
            int r = idx >> 3, g = idx & 7;
            const __nv_bfloat16* src = (arr ? g_kbl : g_kbh)
                + ((size_t)bh * TT + c0 + r) * EE + g * 8;
            cpa16((arr ? bKl : bKh) + (r * KSTR + g * 8) * 2, src);
        }
        #pragma unroll
        for (int l = 0; l < 4; l++) {
            int s = tid + l * 256;
            int arr = s >> 9, idx = s & 511;
            int r = idx >> 3, g = idx & 7;
            const __nv_bfloat16* src = (arr ? g_vbl : g_vbh)
                + ((size_t)bh * EE + r) * TT + c0 + g * 8;
            cpa16((arr ? bVl : bVh) + (r * KSTR + g * 8) * 2, src);
        }
        cp_commit();
    };

    const int nkt = 2 * qt + 2;
    issueKV(0, 0);
    issueKV(64, 1);

    // Q fragments, register-resident (Q pre-scaled by 0.125*log2e)
    const int ra = r0 + wid * 16 + lg, rb = ra + 8;
    uint32_t qh[4][4], ql[4][4];
    {
        const __nv_bfloat16* qhp = g_qbh + (size_t)bh * TT * EE;
        const __nv_bfloat16* qlp = g_qbl + (size_t)bh * TT * EE;
        #pragma unroll
        for (int ks = 0; ks < 4; ks++) {
            int e0 = ks * 16 + 2 * lt;
            qh[ks][0] = *(const uint32_t*)(qhp + (size_t)ra * EE + e0);
            qh[ks][1] = *(const uint32_t*)(qhp + (size_t)rb * EE + e0);
            qh[ks][2] = *(const uint32_t*)(qhp + (size_t)ra * EE + e0 + 8);
            qh[ks][3] = *(const uint32_t*)(qhp + (size_t)rb * EE + e0 + 8);
            ql[ks][0] = *(const uint32_t*)(qlp + (size_t)ra * EE + e0);
            ql[ks][1] = *(const uint32_t*)(qlp + (size_t)rb * EE + e0);
            ql[ks][2] = *(const uint32_t*)(qlp + (size_t)ra * EE + e0 + 8);
            ql[ks][3] = *(const uint32_t*)(qlp + (size_t)rb * EE + e0 + 8);
        }
    }

    float os[8][4] = {};
    float mi_a = -INFINITY, mi_b = -INFINITY, li_a = 0.f, li_b = 0.f;

    for (int kt = 0; kt < nkt; kt++) {
        const int c0 = kt * 64;
        const int buf = kt % 3;
        const uint32_t uKhB = ub + buf * KVBYTES;
        const uint32_t uKlB = ub + (3 + buf) * KVBYTES;
        const uint32_t uVhB = ub + (6 + buf) * KVBYTES;
        const uint32_t uVlB = ub + (9 + buf) * KVBYTES;

        cp_wait<1>();
        __syncthreads();

        // distance-2 prefetch, hoisted: buffer (kt+2)%3 is free right here
        issueKV(kt + 2 < nkt ? c0 + 128 : 0, (kt + 2) % 3);

        // S = Q K^T (3 compensated terms)
        float cs[8][4] = {};
        #pragma unroll
        for (int ks = 0; ks < 4; ks++) {
            const uint32_t co = ks * 16 + kcol;
            #pragma unroll
            for (int jp = 0; jp < 4; jp++) {
                uint32_t kh[4], kl[4];
                uint32_t off = (((jp*16 + krow) * KSTR) + co) * 2;
                ldm4(kh, uKhB + off);
                ldm4(kl, uKlB + off);
                mma_bf16(cs[2*jp],     qh[ks], kh[0], kh[1]);
                mma_bf16(cs[2*jp + 1], qh[ks], kh[2], kh[3]);
                mma_bf16(cs[2*jp],     ql[ks], kh[0], kh[1]);
                mma_bf16(cs[2*jp + 1], ql[ks], kh[2], kh[3]);
                mma_bf16(cs[2*jp],     qh[ks], kl[0], kl[1]);
                mma_bf16(cs[2*jp + 1], qh[ks], kl[2], kl[3]);
            }
        }

        if (kt >= 2 * qt) {  // causal mask (only last two tiles)
            #pragma unroll
            for (int jt = 0; jt < 8; jt++)
                #pragma unroll
                for (int cc = 0; cc < 2; cc++) {
                    int col = c0 + jt * 8 + 2 * lt + cc;
                    if (col > ra) cs[jt][cc]     = -1e30f;
                    if (col > rb) cs[jt][2 + cc] = -1e30f;
                }
        }

        // online softmax (log2 domain) over rows ra / rb
        float ma = -1e30f, mb = -1e30f;
        #pragma unroll
        for (int jt = 0; jt < 8; jt++) {
            ma = fmaxf(ma, fmaxf(cs[jt][0], cs[jt][1]));
            mb = fmaxf(mb, fmaxf(cs[jt][2], cs[jt][3]));
        }
        ma = fmaxf(ma, __shfl_xor_sync(0xffffffffu, ma, 1));
        ma = fmaxf(ma, __shfl_xor_sync(0xffffffffu, ma, 2));
        mb = fmaxf(mb, __shfl_xor_sync(0xffffffffu, mb, 1));
        mb = fmaxf(mb, __shfl_xor_sync(0xffffffffu, mb, 2));
        float nma = fmaxf(mi_a, ma), nmb = fmaxf(mi_b, mb);
        float ca = exp2f(mi_a - nma), cb = exp2f(mi_b - nmb);
        float sa = 0.f, sb = 0.f;
        #pragma unroll
        for (int jt = 0; jt < 8; jt++) {
            cs[jt][0] = exp2f(cs[jt][0] - nma); sa += cs[jt][0];
            cs[jt][1] = exp2f(cs[jt][1] - nma); sa += cs[jt][1];
            cs[jt][2] = exp2f(cs[jt][2] - nmb); sb += cs[jt][2];
            cs[jt][3] = exp2f(cs[jt][3] - nmb); sb += cs[jt][3];
        }
        sa += __shfl_xor_sync(0xffffffffu, sa, 1);
        sa += __shfl_xor_sync(0xffffffffu, sa, 2);
        sb += __shfl_xor_sync(0xffffffffu, sb, 1);
        sb += __shfl_xor_sync(0xffffffffu, sb, 2);
        li_a = li_a * ca + sa; mi_a = nma;
        li_b = li_b * cb + sb; mi_b = nmb;
        #pragma unroll
        for (int jt = 0; jt < 8; jt++) {
            os[jt][0] *= ca; os[jt][1] *= ca;
            os[jt][2] *= cb; os[jt][3] *= cb;
        }

        // P fragments (hi/lo) straight from registers
        uint32_t phi[4][4], plo[4][4];
        #pragma unroll
        for (int cc = 0; cc < 4; cc++) {
            pack_hilo(cs[2*cc][0],   cs[2*cc][1],   phi[cc][0], plo[cc][0]);
            pack_hilo(cs[2*cc][2],   cs[2*cc][3],   phi[cc][1], plo[cc][1]);
            pack_hilo(cs[2*cc+1][0], cs[2*cc+1][1], phi[cc][2], plo[cc][2]);
            pack_hilo(cs[2*cc+1][2], cs[2*cc+1][3], phi[cc][3], plo[cc][3]);
        }

        // O += P V (3 compensated terms)
        #pragma unroll
        for (int cc = 0; cc < 4; cc++) {
            const uint32_t co = cc * 16 + kcol;
            #pragma unroll
            for (int jp = 0; jp < 4; jp++) {
                uint32_t vh[4], vl[4];
                uint32_t off = (((jp*16 + krow) * KSTR) + co) * 2;
                ldm4(vh, uVhB + off);
                ldm4(vl, uVlB + off);
                mma_bf16(os[2*jp],     phi[cc], vh[0], vh[1]);
                mma_bf16(os[2*jp + 1], phi[cc], vh[2], vh[3]);
                mma_bf16(os[2*jp],     plo[cc], vh[0], vh[1]);
                mma_bf16(os[2*jp + 1], plo[cc], vh[2], vh[3]);
                mma_bf16(os[2*jp],     phi[cc], vl[0], vl[1]);
                mma_bf16(os[2*jp + 1], phi[cc], vl[2], vl[3]);
            }
        }
    }

    // epilogue: normalize, write [b,h,t,e]
    const float ia = 1.0f / li_a, ib = 1.0f / li_b;
    #pragma unroll
    for (int jt = 0; jt < 8; jt++) {
        int e0 = jt * 8 + 2 * lt;
        float2 wa = make_float2(os[jt][0] * ia, os[jt][1] * ia);
        float2 wb = make_float2(os[jt][2] * ib, os[jt][3] * ib);
        *(float2*)(g_o + ((size_t)bh * TT + ra) * EE + e0) = wa;
        *(float2*)(g_o + ((size_t)bh * TT + rb) * EE + e0) = wb;
    }
}

// ---------------------------------------------------------------------------
// Kernel 3a: out = bias broadcast
// ---------------------------------------------------------------------------
__global__ __launch_bounds__(256) void init_out(const float* __restrict__ bu,
                                                float* __restrict__ out)
{
    int i = blockIdx.x * 256 + threadIdx.x;
    out[i] = bu[i & 63];
}

// ---------------------------------------------------------------------------
// Kernel 3b: output projection as sum of per-head GEMMs (coalesced A loads).
// ---------------------------------------------------------------------------
__global__ __launch_bounds__(256) void proj_kernel(
    const float* __restrict__ Wu,
    float* __restrict__ out)
{
    __shared__ __align__(16) float As[64*68];  // [e][m] transposed on write
    __shared__ __align__(16) float Bs[64*68];  // [e][n]

    const int m0 = blockIdx.x * 64;
    const int tid = threadIdx.x;
    const int ty = tid >> 4, tx = tid & 15;
    const int b = m0 >> 11, t0 = m0 & 2047;

    float acc[4][4] = {};

    for (int hh = 0; hh < 4; hh++) {
        const int h = blockIdx.y * 4 + hh;
        __syncthreads();
        const float* op = g_o + ((size_t)(b * HH + h) * TT + t0) * EE;
        for (int s = tid; s < 1024; s += 256) {
            int r = s >> 4, g = s & 15;
            float4 v = *(const float4*)(op + r * EE + g * 4);
            As[(g*4 + 0)*68 + r] = v.x;
            As[(g*4 + 1)*68 + r] = v.y;
            As[(g*4 + 2)*68 + r] = v.z;
            As[(g*4 + 3)*68 + r] = v.w;
        }
        for (int s = tid; s < 1024; s += 256) {
            int e = s >> 4, g = s & 15;
            *(float4*)(Bs + e*68 + g*4) =
                *(const float4*)(Wu + (size_t)(e * HH + h) * EE + g * 4);
        }
        __syncthreads();

        #pragma unroll 8
        for (int e = 0; e < 64; e++) {
            float a[4], bv[4];
            ld4(a,  As + e*68 + ty*4);
            ld4(bv, Bs + e*68 + tx*4);
            #pragma unroll
            for (int i = 0; i < 4; i++)
                #pragma unroll
                for (int j = 0; j < 4; j++)
                    acc[i][j] += a[i] * bv[j];
        }
    }

    #pragma unroll
    for (int i = 0; i < 4; i++) {
        int gm = m0 + ty*4 + i;
        #pragma unroll
        for (int j = 0; j < 4; j++)
            atomicAdd(out + (size_t)gm * EE + tx*4 + j, acc[i][j]);
    }
}

// ---------------------------------------------------------------------------
extern "C" void kernel_launch(void* const* d_in, const int* in_sizes, int n_in,
                              void* d_out, int out_size)
{
    const float* inp = (const float*)d_in[0];
    // d_in[1] is the causal mask; causality is implemented directly.
    const float* Wq = (const float*)d_in[2];
    const float* Wk = (const float*)d_in[3];
    const float* Wv = (const float*)d_in[4];
    const float* Wu = (const float*)d_in[5];
    const float* bu = (const float*)d_in[6];
    float* out = (float*)d_out;

    cudaFuncSetAttribute(qkv_mma,
                         cudaFuncAttributeMaxDynamicSharedMemorySize, QKV_SMEM);
    cudaFuncSetAttribute(attn_mma,
                         cudaFuncAttributeMaxDynamicSharedMemorySize, ATTN_SMEM);

    conv_x<<<MM*DIN/1024, 256>>>(inp);
    conv_w<<<dim3(DIN/32, EH/32, 3), 256>>>(Wq, Wk, Wv);

    qkv_mma<<<dim3(MM/128, EH/128, 3), 256, QKV_SMEM>>>();

    conv_qkv<<<dim3(CONVN/4096, 3), 256>>>();

    attn_mma<<<dim3(TT/128, BB*HH), 256, ATTN_SMEM>>>();

    init_out<<<(MM*EE)/256, 256>>>(bu, out);
    proj_kernel<<<dim3(MM/64, 4), 256>>>(Wu, out);
}

// round 15
// speedup vs baseline: 1.0318x; 1.0211x over previous
#include <cuda_runtime.h>
#include <cuda_bf16.h>
#include <math.h>
#include <stdint.h>

#define BB 2
#define TT 2048
#define DIN 1024
#define EE 64
#define HH 16
#define EH 1024
#define MM (BB*TT)

// bf16 split operands for QKV GEMM
__device__ __align__(16) __nv_bfloat16 g_xhi[MM*DIN];
__device__ __align__(16) __nv_bfloat16 g_xlo[MM*DIN];
__device__ __align__(16) __nv_bfloat16 g_wthi[3*EH*DIN];   // [z][n][k]
__device__ __align__(16) __nv_bfloat16 g_wtlo[3*EH*DIN];
// fp32 staging: q,k in [b,h,t,e]; v in [b,h,e,t]
__device__ __align__(16) float g_qf[BB*HH*TT*EE];
__device__ __align__(16) float g_kf[BB*HH*TT*EE];
__device__ __align__(16) float g_vf[BB*HH*EE*TT];
// bf16 hi/lo for attention (q,k [b,h,t,e]; v [b,h,e,t]); q scaled 0.125*log2e
__device__ __align__(16) __nv_bfloat16 g_qbh[BB*HH*TT*EE];
__device__ __align__(16) __nv_bfloat16 g_qbl[BB*HH*TT*EE];
__device__ __align__(16) __nv_bfloat16 g_kbh[BB*HH*TT*EE];
__device__ __align__(16) __nv_bfloat16 g_kbl[BB*HH*TT*EE];
__device__ __align__(16) __nv_bfloat16 g_vbh[BB*HH*EE*TT];
__device__ __align__(16) __nv_bfloat16 g_vbl[BB*HH*EE*TT];
// attention output [b,h,t,e] fp32
__device__ __align__(16) float g_o[BB*HH*TT*EE];

__device__ __forceinline__ void ld4(float* d, const float* s) {
    float4 t = *(const float4*)s;
    d[0] = t.x; d[1] = t.y; d[2] = t.z; d[3] = t.w;
}
__device__ __forceinline__ void cpa16(uint32_t dst, const void* src) {
    asm volatile("cp.async.cg.shared.global [%0], [%1], 16;\n" :: "r"(dst), "l"(src));
}
__device__ __forceinline__ void cp_commit() {
    asm volatile("cp.async.commit_group;\n");
}
template<int N> __device__ __forceinline__ void cp_wait() {
    asm volatile("cp.async.wait_group %0;\n" :: "n"(N));
}
__device__ __forceinline__ uint32_t smem_u32(const void* p) {
    uint32_t a;
    asm("{ .reg .u64 t; cvta.to.shared.u64 t, %1; cvt.u32.u64 %0, t; }" : "=r"(a) : "l"(p));
    return a;
}
__device__ __forceinline__ void mma_bf16(float* c, const uint32_t* a,
                                         uint32_t b0, uint32_t b1) {
    asm volatile(
        "mma.sync.aligned.m16n8k16.row.col.f32.bf16.bf16.f32 "
        "{%0,%1,%2,%3}, {%4,%5,%6,%7}, {%8,%9}, {%0,%1,%2,%3};"
        : "+f"(c[0]), "+f"(c[1]), "+f"(c[2]), "+f"(c[3])
        : "r"(a[0]), "r"(a[1]), "r"(a[2]), "r"(a[3]), "r"(b0), "r"(b1));
}
__device__ __forceinline__ void ldm4(uint32_t* r, uint32_t addr) {
    asm volatile("ldmatrix.sync.aligned.m8n8.x4.shared.b16 {%0,%1,%2,%3}, [%4];"
        : "=r"(r[0]), "=r"(r[1]), "=r"(r[2]), "=r"(r[3]) : "r"(addr));
}
// pack (f0 -> low half, f1 -> high half) into bf16x2 hi + residual lo
__device__ __forceinline__ void pack_hilo(float f0, float f1,
                                          uint32_t& hi, uint32_t& lo) {
    __nv_bfloat162 h = __floats2bfloat162_rn(f0, f1);
    float r0 = f0 - __bfloat162float(h.x);
    float r1 = f1 - __bfloat162float(h.y);
    __nv_bfloat162 l = __floats2bfloat162_rn(r0, r1);
    hi = *reinterpret_cast<uint32_t*>(&h);
    lo = *reinterpret_cast<uint32_t*>(&l);
}

// ---------------------------------------------------------------------------
// Prep: X f32 -> bf16 hi/lo
// ---------------------------------------------------------------------------
__global__ __launch_bounds__(256) void conv_x(const float* __restrict__ x)
{
    int i = (blockIdx.x * 256 + threadIdx.x) * 4;
    float4 v = *(const float4*)(x + i);
    uint32_t h01, l01, h23, l23;
    pack_hilo(v.x, v.y, h01, l01);
    pack_hilo(v.z, v.w, h23, l23);
    *(uint32_t*)(g_xhi + i)     = h01;
    *(uint32_t*)(g_xhi + i + 2) = h23;
    *(uint32_t*)(g_xlo + i)     = l01;
    *(uint32_t*)(g_xlo + i + 2) = l23;
}

// ---------------------------------------------------------------------------
// Prep: W [k][n] f32 -> Wt [n][k] bf16 hi/lo, for each of Wq,Wk,Wv
// ---------------------------------------------------------------------------
__global__ __launch_bounds__(256) void conv_w(
    const float* __restrict__ Wq, const float* __restrict__ Wk,
    const float* __restrict__ Wv)
{
    const int z = blockIdx.z;
    const float* W = (z == 0) ? Wq : (z == 1) ? Wk : Wv;
    __shared__ float t[32][33];
    const int k0 = blockIdx.x * 32, n0 = blockIdx.y * 32;
    const int x = threadIdx.x & 31, y = threadIdx.x >> 5;
    #pragma unroll
    for (int i = 0; i < 32; i += 8)
        t[y + i][x] = W[(k0 + y + i) * EH + n0 + x];
    __syncthreads();
    #pragma unroll
    for (int i = 0; i < 32; i += 8) {
        float v = t[x][y + i];
        __nv_bfloat16 hi = __float2bfloat16(v);
        __nv_bfloat16 lo = __float2bfloat16(v - __bfloat162float(hi));
        size_t idx = (size_t)z * EH * DIN + (size_t)(n0 + y + i) * DIN + k0 + x;
        g_wthi[idx] = hi;
        g_wtlo[idx] = lo;
    }
}

// ---------------------------------------------------------------------------
// Kernel 1: QKV via mma.sync bf16 (hi/lo 3-term compensation).
// Triple-buffered cp.async, k-tile 32 (96 iters), distance-2 prefetch,
// ONE wait + ONE barrier per k-tile. ldmatrix frags; fp32 staging epilogue.
// CTA 128m x 128n, 8 warps (2m x 4n), warp tile 64x32.  (R11 exact.)
// ---------------------------------------------------------------------------
#define ASTR 40
#define QB (128*ASTR*2)        // 10240 B per operand per stage
#define QKV_SMEM (6*QB)        // A0 A1 A2 B0 B1 B2 = 61440 B

__global__ __launch_bounds__(256, 2) void qkv_mma()
{
    extern __shared__ __align__(16) char qsm[];
    const uint32_t ub = smem_u32(qsm);

    const int z = blockIdx.z;
    const int m0 = blockIdx.x * 128;
    const int n0 = blockIdx.y * 128;
    const int tid = threadIdx.x;
    const int wid = tid >> 5, lane = tid & 31;
    const int wm = wid >> 2, wn = wid & 3;
    const int lg = lane >> 2, lt = lane & 3;
    const int arow = ((lane >> 3) & 1) * 8 + (lane & 7);
    const int acol = ((lane >> 4) & 1) * 8;
    const int brow = ((lane >> 4) & 1) * 8 + (lane & 7);
    const int bcol = ((lane >> 3) & 1) * 8;

    const __nv_bfloat16* whi = g_wthi + (size_t)z * EH * DIN;
    const __nv_bfloat16* wlo = g_wtlo + (size_t)z * EH * DIN;

    auto fill = [&](int c, int stg) {
        const int pass = c >> 5;
        const int k0 = (c & 31) * 32;
        const __nv_bfloat16* A = (pass == 1) ? g_xlo : g_xhi;
        const __nv_bfloat16* B = (pass == 2) ? wlo : whi;
        const uint32_t ab = ub + stg * QB;
        const uint32_t bb = ub + (3 + stg) * QB;
        #pragma unroll
        for (int l = 0; l < 2; l++) {
            int s = tid + l * 256, r = s >> 2, cg = s & 3;
            uint32_t off = (r * ASTR + cg * 8) * 2;
            cpa16(ab + off, A + (size_t)(m0 + r) * DIN + k0 + cg * 8);
            cpa16(bb + off, B + (size_t)(n0 + r) * DIN + k0 + cg * 8);
        }
        cp_commit();
    };

    float acc[4][4][4] = {};

    fill(0, 0);
    fill(1, 1);
    for (int c = 0; c < 96; c++) {
        const int stg = c % 3;
        cp_wait<1>();        // tile c complete; tile c+1 may be in flight
        __syncthreads();     // all warps done with buf (c+2)%3 (iter c-1)

        fill(c + 2 < 96 ? c + 2 : 0, (c + 2) % 3);   // distance-2 prefetch

        const uint32_t sAb = ub + stg * QB;
        const uint32_t sBb = ub + (3 + stg) * QB;
        #pragma unroll
        for (int ks = 0; ks < 2; ks++) {
            uint32_t af[4][4], bfr[2][4];
            #pragma unroll
            for (int i = 0; i < 4; i++)
                ldm4(af[i], sAb + (((wm*64 + i*16 + arow) * ASTR) + ks*16 + acol) * 2);
            #pragma unroll
            for (int jp = 0; jp < 2; jp++)
                ldm4(bfr[jp], sBb + (((wn*32 + jp*16 + brow) * ASTR) + ks*16 + bcol) * 2);
            #pragma unroll
            for (int i = 0; i < 4; i++)
                #pragma unroll
                for (int j = 0; j < 4; j++)
                    mma_bf16(acc[i][j], af[i], bfr[j >> 1][(j & 1)*2], bfr[j >> 1][(j & 1)*2 + 1]);
        }
    }

    // epilogue: de-interleave heads (n = e*16 + h), fp32 staging.
    float* dst = (z == 0) ? g_qf : (z == 1) ? g_kf : g_vf;
    const int emajor = (z == 2);
    #pragma unroll
    for (int i = 0; i < 4; i++) {
        #pragma unroll
        for (int j = 0; j < 4; j++) {
            #pragma unroll
            for (int rr = 0; rr < 2; rr++) {
                int m = m0 + wm * 64 + i * 16 + lg + rr * 8;
                int b = m >> 11, t = m & 2047;
                #pragma unroll
                for (int cc = 0; cc < 2; cc++) {
                    int n = n0 + wn * 32 + j * 8 + lt * 2 + cc;
                    int e = n >> 4, h = n & 15;
                    size_t bh = (size_t)(b * HH + h);
                    float v = acc[i][j][rr * 2 + cc];
                    if (emajor) dst[(bh * EE + e) * TT + t] = v;
                    else        dst[(bh * TT + t) * EE + e] = v;
                }
            }
        }
    }
}

// ---------------------------------------------------------------------------
// conv_qkv: fp32 staging -> bf16 hi/lo (Q scaled 0.125*log2(e) for exp2f).
// 4 independent float4 per thread (batched loads -> MLP 4).
// ---------------------------------------------------------------------------
#define CONVN (BB*HH*TT*EE)     // elements per tensor
#define CONVSTRIDE (CONVN/4)    // 4 chunks

__global__ __launch_bounds__(256) void conv_qkv()
{
    const int z = blockIdx.y;
    const float* src = (z == 0) ? g_qf : (z == 1) ? g_kf : g_vf;
    __nv_bfloat16* dh = (z == 0) ? g_qbh : (z == 1) ? g_kbh : g_vbh;
    __nv_bfloat16* dl = (z == 0) ? g_qbl : (z == 1) ? g_kbl : g_vbl;
    const float sc = (z == 0) ? 0.125f * 1.4426950408889634f : 1.0f;
    const size_t base = ((size_t)blockIdx.x * 256 + threadIdx.x) * 4;

    float4 v[4];
    #pragma unroll
    for (int k = 0; k < 4; k++)
        v[k] = *(const float4*)(src + base + (size_t)k * CONVSTRIDE);

    #pragma unroll
    for (int k = 0; k < 4; k++) {
        size_t i = base + (size_t)k * CONVSTRIDE;
        float4 w = v[k];
        w.x *= sc; w.y *= sc; w.z *= sc; w.w *= sc;
        uint32_t h01, l01, h23, l23;
        pack_hilo(w.x, w.y, h01, l01);
        pack_hilo(w.z, w.w, h23, l23);
        *(uint32_t*)(dh + i)     = h01;
        *(uint32_t*)(dh + i + 2) = h23;
        *(uint32_t*)(dl + i)     = l01;
        *(uint32_t*)(dl + i + 2) = l23;
    }
}

// ---------------------------------------------------------------------------
// Kernel 2: flash-attention on mma.sync, causal, hi/lo compensated, ldmatrix.
// Triple-buffered K/V (hi/lo), distance-2 prefetch AFTER the S-phase (the
// R11-proven placement: softmax leaves the LSU idle there), ONE wait + ONE
// barrier per iteration. Softmax in log2 domain. Key tiles of 64.
// CTA = 128 rows of one (b,h); 8 warps x 16 rows.  (R11 exact.)
// ---------------------------------------------------------------------------
#define KSTR 72
#define KVBYTES (64*KSTR*2)     // 9216 B per buffer
#define ATTN_SMEM (12*KVBYTES)  // Kh x3, Kl x3, Vh x3, Vl x3 = 110592 B

__global__ __launch_bounds__(256) void attn_mma()
{
    extern __shared__ __align__(16) char asm_[];
    const uint32_t ub = smem_u32(asm_);

    const int qt = (int)(gridDim.x - 1) - (int)blockIdx.x;  // big tiles first
    const int bh = blockIdx.y;
    const int r0 = qt * 128;
    const int tid = threadIdx.x;
    const int wid = tid >> 5, lane = tid & 31;
    const int lg = lane >> 2, lt = lane & 3;
    const int krow = ((lane >> 4) & 1) * 8 + (lane & 7);
    const int kcol = ((lane >> 3) & 1) * 8;

    auto issueKV = [&](int c0, int buf) {
        const uint32_t bKh = ub + buf * KVBYTES;
        const uint32_t bKl = ub + (3 + buf) * KVBYTES;
        const uint32_t bVh = ub + (6 + buf) * KVBYTES;
        const uint32_t bVl = ub + (9 + buf) * KVBYTES;
        #pragma unroll
        for (int l = 0; l < 4; l++) {
            int s = tid + l * 256;
            int arr = s >> 9, idx = s & 511;
            int r = idx >> 3, g = idx & 7;
            const __nv_bfloat16* src = (arr ? g_kbl : g_kbh)
                + ((size_t)bh * TT + c0 + r) * EE + g * 8;
            cpa16((arr ? bKl : bKh) + (r * KSTR + g * 8) * 2, src);
        }
        #pragma unroll
        for (int l = 0; l < 4; l++) {
            int s = tid + l * 256;
            int arr = s >> 9, idx = s & 511;
            int r = idx >> 3, g = idx & 7;
            const __nv_bfloat16* src = (arr ? g_vbl : g_vbh)
                + ((size_t)bh * EE + r) * TT + c0 + g * 8;
            cpa16((arr ? bVl : bVh) + (r * KSTR + g * 8) * 2, src);
        }
        cp_commit();
    };

    const int nkt = 2 * qt + 2;
    issueKV(0, 0);
    issueKV(64, 1);

    // Q fragments, register-resident (Q pre-scaled by 0.125*log2e)
    const int ra = r0 + wid * 16 + lg, rb = ra + 8;
    uint32_t qh[4][4], ql[4][4];
    {
        const __nv_bfloat16* qhp = g_qbh + (size_t)bh * TT * EE;
        const __nv_bfloat16* qlp = g_qbl + (size_t)bh * TT * EE;
        #pragma unroll
        for (int ks = 0; ks < 4; ks++) {
            int e0 = ks * 16 + 2 * lt;
            qh[ks][0] = *(const uint32_t*)(qhp + (size_t)ra * EE + e0);
            qh[ks][1] = *(const uint32_t*)(qhp + (size_t)rb * EE + e0);
            qh[ks][2] = *(const uint32_t*)(qhp + (size_t)ra * EE + e0 + 8);
            qh[ks][3] = *(const uint32_t*)(qhp + (size_t)rb * EE + e0 + 8);
            ql[ks][0] = *(const uint32_t*)(qlp + (size_t)ra * EE + e0);
            ql[ks][1] = *(const uint32_t*)(qlp + (size_t)rb * EE + e0);
            ql[ks][2] = *(const uint32_t*)(qlp + (size_t)ra * EE + e0 + 8);
            ql[ks][3] = *(const uint32_t*)(qlp + (size_t)rb * EE + e0 + 8);
        }
    }

    float os[8][4] = {};
    float mi_a = -INFINITY, mi_b = -INFINITY, li_a = 0.f, li_b = 0.f;

    for (int kt = 0; kt < nkt; kt++) {
        const int c0 = kt * 64;
        const int buf = kt % 3;
        const uint32_t uKhB = ub + buf * KVBYTES;
        const uint32_t uKlB = ub + (3 + buf) * KVBYTES;
        const uint32_t uVhB = ub + (6 + buf) * KVBYTES;
        const uint32_t uVlB = ub + (9 + buf) * KVBYTES;

        cp_wait<1>();
        __syncthreads();

        // S = Q K^T (3 compensated terms)
        float cs[8][4] = {};
        #pragma unroll
        for (int ks = 0; ks < 4; ks++) {
            const uint32_t co = ks * 16 + kcol;
            #pragma unroll
            for (int jp = 0; jp < 4; jp++) {
                uint32_t kh[4], kl[4];
                uint32_t off = (((jp*16 + krow) * KSTR) + co) * 2;
                ldm4(kh, uKhB + off);
                ldm4(kl, uKlB + off);
                mma_bf16(cs[2*jp],     qh[ks], kh[0], kh[1]);
                mma_bf16(cs[2*jp + 1], qh[ks], kh[2], kh[3]);
                mma_bf16(cs[2*jp],     ql[ks], kh[0], kh[1]);
                mma_bf16(cs[2*jp + 1], ql[ks], kh[2], kh[3]);
                mma_bf16(cs[2*jp],     qh[ks], kl[0], kl[1]);
                mma_bf16(cs[2*jp + 1], qh[ks], kl[2], kl[3]);
            }
        }

        // distance-2 prefetch (R11 placement: overlaps softmax + PV)
        issueKV(kt + 2 < nkt ? c0 + 128 : 0, (kt + 2) % 3);

        if (kt >= 2 * qt) {  // causal mask (only last two tiles)
            #pragma unroll
            for (int jt = 0; jt < 8; jt++)
                #pragma unroll
                for (int cc = 0; cc < 2; cc++) {
                    int col = c0 + jt * 8 + 2 * lt + cc;
                    if (col > ra) cs[jt][cc]     = -1e30f;
                    if (col > rb) cs[jt][2 + cc] = -1e30f;
                }
        }

        // online softmax (log2 domain) over rows ra / rb
        float ma = -1e30f, mb = -1e30f;
        #pragma unroll
        for (int jt = 0; jt < 8; jt++) {
            ma = fmaxf(ma, fmaxf(cs[jt][0], cs[jt][1]));
            mb = fmaxf(mb, fmaxf(cs[jt][2], cs[jt][3]));
        }
        ma = fmaxf(ma, __shfl_xor_sync(0xffffffffu, ma, 1));
        ma = fmaxf(ma, __shfl_xor_sync(0xffffffffu, ma, 2));
        mb = fmaxf(mb, __shfl_xor_sync(0xffffffffu, mb, 1));
        mb = fmaxf(mb, __shfl_xor_sync(0xffffffffu, mb, 2));
        float nma = fmaxf(mi_a, ma), nmb = fmaxf(mi_b, mb);
        float ca = exp2f(mi_a - nma), cb = exp2f(mi_b - nmb);
        float sa = 0.f, sb = 0.f;
        #pragma unroll
        for (int jt = 0; jt < 8; jt++) {
            cs[jt][0] = exp2f(cs[jt][0] - nma); sa += cs[jt][0];
            cs[jt][1] = exp2f(cs[jt][1] - nma); sa += cs[jt][1];
            cs[jt][2] = exp2f(cs[jt][2] - nmb); sb += cs[jt][2];
            cs[jt][3] = exp2f(cs[jt][3] - nmb); sb += cs[jt][3];
        }
        sa += __shfl_xor_sync(0xffffffffu, sa, 1);
        sa += __shfl_xor_sync(0xffffffffu, sa, 2);
        sb += __shfl_xor_sync(0xffffffffu, sb, 1);
        sb += __shfl_xor_sync(0xffffffffu, sb, 2);
        li_a = li_a * ca + sa; mi_a = nma;
        li_b = li_b * cb + sb; mi_b = nmb;
        #pragma unroll
        for (int jt = 0; jt < 8; jt++) {
            os[jt][0] *= ca; os[jt][1] *= ca;
            os[jt][2] *= cb; os[jt][3] *= cb;
        }

        // P fragments (hi/lo) straight from registers
        uint32_t phi[4][4], plo[4][4];
        #pragma unroll
        for (int cc = 0; cc < 4; cc++) {
            pack_hilo(cs[2*cc][0],   cs[2*cc][1],   phi[cc][0], plo[cc][0]);
            pack_hilo(cs[2*cc][2],   cs[2*cc][3],   phi[cc][1], plo[cc][1]);
            pack_hilo(cs[2*cc+1][0], cs[2*cc+1][1], phi[cc][2], plo[cc][2]);
            pack_hilo(cs[2*cc+1][2], cs[2*cc+1][3], phi[cc][3], plo[cc][3]);
        }

        // O += P V (3 compensated terms)
        #pragma unroll
        for (int cc = 0; cc < 4; cc++) {
            const uint32_t co = cc * 16 + kcol;
            #pragma unroll
            for (int jp = 0; jp < 4; jp++) {
                uint32_t vh[4], vl[4];
                uint32_t off = (((jp*16 + krow) * KSTR) + co) * 2;
                ldm4(vh, uVhB + off);
                ldm4(vl, uVlB + off);
                mma_bf16(os[2*jp],     phi[cc], vh[0], vh[1]);
                mma_bf16(os[2*jp + 1], phi[cc], vh[2], vh[3]);
                mma_bf16(os[2*jp],     plo[cc], vh[0], vh[1]);
                mma_bf16(os[2*jp + 1], plo[cc], vh[2], vh[3]);
                mma_bf16(os[2*jp],     phi[cc], vl[0], vl[1]);
                mma_bf16(os[2*jp + 1], phi[cc], vl[2], vl[3]);
            }
        }
    }

    // epilogue: normalize, write [b,h,t,e]
    const float ia = 1.0f / li_a, ib = 1.0f / li_b;
    #pragma unroll
    for (int jt = 0; jt < 8; jt++) {
        int e0 = jt * 8 + 2 * lt;
        float2 wa = make_float2(os[jt][0] * ia, os[jt][1] * ia);
        float2 wb = make_float2(os[jt][2] * ib, os[jt][3] * ib);
        *(float2*)(g_o + ((size_t)bh * TT + ra) * EE + e0) = wa;
        *(float2*)(g_o + ((size_t)bh * TT + rb) * EE + e0) = wb;
    }
}

// ---------------------------------------------------------------------------
// Kernel 3a: out = bias broadcast
// ---------------------------------------------------------------------------
__global__ __launch_bounds__(256) void init_out(const float* __restrict__ bu,
                                                float* __restrict__ out)
{
    int i = blockIdx.x * 256 + threadIdx.x;
    out[i] = bu[i & 63];
}

// ---------------------------------------------------------------------------
// Kernel 3b: output projection as sum of per-head GEMMs (coalesced A loads).
// ---------------------------------------------------------------------------
__global__ __launch_bounds__(256) void proj_kernel(
    const float* __restrict__ Wu,
    float* __restrict__ out)
{
    __shared__ __align__(16) float As[64*68];  // [e][m] transposed on write
    __shared__ __align__(16) float Bs[64*68];  // [e][n]

    const int m0 = blockIdx.x * 64;
    const int tid = threadIdx.x;
    const int ty = tid >> 4, tx = tid & 15;
    const int b = m0 >> 11, t0 = m0 & 2047;

    float acc[4][4] = {};

    for (int hh = 0; hh < 4; hh++) {
        const int h = blockIdx.y * 4 + hh;
        __syncthreads();
        const float* op = g_o + ((size_t)(b * HH + h) * TT + t0) * EE;
        for (int s = tid; s < 1024; s += 256) {
            int r = s >> 4, g = s & 15;
            float4 v = *(const float4*)(op + r * EE + g * 4);
            As[(g*4 + 0)*68 + r] = v.x;
            As[(g*4 + 1)*68 + r] = v.y;
            As[(g*4 + 2)*68 + r] = v.z;
            As[(g*4 + 3)*68 + r] = v.w;
        }
        for (int s = tid; s < 1024; s += 256) {
            int e = s >> 4, g = s & 15;
            *(float4*)(Bs + e*68 + g*4) =
                *(const float4*)(Wu + (size_t)(e * HH + h) * EE + g * 4);
        }
        __syncthreads();

        #pragma unroll 8
        for (int e = 0; e < 64; e++) {
            float a[4], bv[4];
            ld4(a,  As + e*68 + ty*4);
            ld4(bv, Bs + e*68 + tx*4);
            #pragma unroll
            for (int i = 0; i < 4; i++)
                #pragma unroll
                for (int j = 0; j < 4; j++)
                    acc[i][j] += a[i] * bv[j];
        }
    }

    #pragma unroll
    for (int i = 0; i < 4; i++) {
        int gm = m0 + ty*4 + i;
        #pragma unroll
        for (int j = 0; j < 4; j++)
            atomicAdd(out + (size_t)gm * EE + tx*4 + j, acc[i][j]);
    }
}

// ---------------------------------------------------------------------------
extern "C" void kernel_launch(void* const* d_in, const int* in_sizes, int n_in,
                              void* d_out, int out_size)
{
    const float* inp = (const float*)d_in[0];
    // d_in[1] is the causal mask; causality is implemented directly.
    const float* Wq = (const float*)d_in[2];
    const float* Wk = (const float*)d_in[3];
    const float* Wv = (const float*)d_in[4];
    const float* Wu = (const float*)d_in[5];
    const float* bu = (const float*)d_in[6];
    float* out = (float*)d_out;

    cudaFuncSetAttribute(qkv_mma,
                         cudaFuncAttributeMaxDynamicSharedMemorySize, QKV_SMEM);
    cudaFuncSetAttribute(attn_mma,
                         cudaFuncAttributeMaxDynamicSharedMemorySize, ATTN_SMEM);

    conv_x<<<MM*DIN/1024, 256>>>(inp);
    conv_w<<<dim3(DIN/32, EH/32, 3), 256>>>(Wq, Wk, Wv);

    qkv_mma<<<dim3(MM/128, EH/128, 3), 256, QKV_SMEM>>>();

    conv_qkv<<<dim3(CONVN/4096, 3), 256>>>();

    attn_mma<<<dim3(TT/128, BB*HH), 256, ATTN_SMEM>>>();

    init_out<<<(MM*EE)/256, 256>>>(bu, out);
    proj_kernel<<<dim3(MM/64, 4), 256>>>(Wu, out);
}